// round 12
// baseline (speedup 1.0000x reference)
#include <cuda_runtime.h>
#include <cuda_fp16.h>
#include <cstdint>

// QLinear int4 dequant GEMM via mma.sync fp16 split-precision (sm_80 baseline ISA).
// D[n_out, tok] = W[n,k] @ X^T;  A = dequantized W hi/lo (fp16 split, w to ~2^-23),
// B = x as single fp16 (err ~2^-12, dominates at ~1.4e-4 rel).
// 2 products per step: Wh*X + Wl*X.

#define MM 32
#define KK 4096
#define NN 11008
#define BN 128
#define KSPLIT 8
#define KSPAN (KK / KSPLIT)    // 512
#define KC 128
#define THREADS 256
#define XS 272                 // x smem row stride (bytes): 256 data + 16 pad
#define RS 132                 // res row stride (floats)

__device__ __half g_x[MM * KK];
__device__ float g_part[KSPLIT][MM * NN];

__global__ __launch_bounds__(256)
void split_x(const float* __restrict__ x) {
    int i = blockIdx.x * 256 + threadIdx.x;       // float4 index, 32768 total
    if (i < MM * KK / 4) {
        float4 f = ((const float4*)x)[i];
        __half2 h0 = __floats2half2_rn(f.x, f.y);  // lower = f.x
        __half2 h1 = __floats2half2_rn(f.z, f.w);
        ((uint2*)g_x)[i] = make_uint2(*(uint32_t*)&h0, *(uint32_t*)&h1);
    }
}

__device__ __forceinline__ float dq1(int q, float s, float z) {
    float f = __int_as_float(q | 0x4B000000);   // 2^23 + q
    float t = f - 8388616.0f;                   // exact (Sterbenz): q - 8
    return __fmaf_rn(t, s, z);
}

// dequant int2 (k-even, k-odd) -> packed fp16x2 hi + fp16x2 residual lo
__device__ __forceinline__ void dqpair(int2 q, float2 szv, uint32_t& hi, uint32_t& lo) {
    float s = szv.x, z = szv.y;
    float w0 = dq1(q.x, s, z);
    float w1 = dq1(q.y, s, z);
    uint32_t h;
    asm("cvt.rn.f16x2.f32 %0, %1, %2;" : "=r"(h) : "f"(w1), "f"(w0));  // lower = w0
    __half2 hh = *reinterpret_cast<__half2*>(&h);
    float l0 = w0 - __half2float(hh.x);
    float l1 = w1 - __half2float(hh.y);
    uint32_t l;
    asm("cvt.rn.f16x2.f32 %0, %1, %2;" : "=r"(l) : "f"(l1), "f"(l0));
    hi = h; lo = l;
}

__device__ __forceinline__ void mma16816(float* d, const uint32_t* a, uint32_t b0, uint32_t b1) {
    asm volatile(
        "mma.sync.aligned.m16n8k16.row.col.f32.f16.f16.f32 "
        "{%0,%1,%2,%3}, {%4,%5,%6,%7}, {%8,%9}, {%0,%1,%2,%3};"
        : "+f"(d[0]), "+f"(d[1]), "+f"(d[2]), "+f"(d[3])
        : "r"(a[0]), "r"(a[1]), "r"(a[2]), "r"(a[3]), "r"(b0), "r"(b1));
}

__global__ __launch_bounds__(THREADS)
void qlinear_mma(const int* __restrict__ w, const float* __restrict__ sz)
{
    __shared__ union {
        char xb[MM * XS];          // 8704 B (fp16 x)
        float res[MM][RS];         // 16896 B
    } sm;

    const int tid  = threadIdx.x;
    const int lane = tid & 31;
    const int wid  = tid >> 5;
    const int nb   = blockIdx.x * BN;
    const int kq   = blockIdx.y;
    const int kbeg = kq * KSPAN;
    const int g4   = lane >> 2;   // 0..7
    const int l4   = lane & 3;    // 0..3

    const int r0 = nb + wid * 16 + g4;
    const int* wp0 = w + (size_t)r0 * KK + kbeg;
    const int* wp1 = wp0 + (size_t)8 * KK;
    const float2* szp = (const float2*)sz;

    float d[4][4];
    #pragma unroll
    for (int tg = 0; tg < 4; tg++)
        #pragma unroll
        for (int j = 0; j < 4; j++) d[tg][j] = 0.f;

    for (int kc = 0; kc < KSPAN; kc += KC) {
        __syncthreads();   // previous chunk fully consumed
        // ---- stage x chunk (fp16): 8 KB, one uint4 per thread x2 ----
        {
            int tok = tid >> 3, seg = tid & 7;    // 8 x 32B segs per 256B row... (16B each x 2)
            size_t s = (size_t)tok * KK + kbeg + kc + seg * 16;
            *(uint4*)(sm.xb + tok * XS + seg * 32)      = *(const uint4*)(g_x + s);
            *(uint4*)(sm.xb + tok * XS + seg * 32 + 16) = *(const uint4*)(g_x + s + 8);
        }
        // ---- scales for this chunk's 4 groups, rows r0 / r0+8 ----
        float2 sc0[4], sc1[4];
        {
            int gb = (kbeg + kc) >> 5;
            #pragma unroll
            for (int g = 0; g < 4; g++) {
                sc0[g] = szp[(size_t)(gb + g) * NN + r0];
                sc1[g] = szp[(size_t)(gb + g) * NN + r0 + 8];
            }
        }
        __syncthreads();

        #pragma unroll
        for (int st = 0; st < 8; st++) {          // k16 steps in chunk
            const int koff = kc + st * 16 + l4 * 2;
            int2 q0 = *(const int2*)(wp0 + koff);
            int2 q1 = *(const int2*)(wp1 + koff);
            int2 q2 = *(const int2*)(wp0 + koff + 8);
            int2 q3 = *(const int2*)(wp1 + koff + 8);
            float2 s0 = sc0[st >> 1];
            float2 s1 = sc1[st >> 1];

            uint32_t ah[4], al[4];
            dqpair(q0, s0, ah[0], al[0]);
            dqpair(q1, s1, ah[1], al[1]);
            dqpair(q2, s0, ah[2], al[2]);
            dqpair(q3, s1, ah[3], al[3]);

            #pragma unroll
            for (int tg = 0; tg < 4; tg++) {
                int base = (tg * 8 + g4) * XS + st * 32 + l4 * 4;
                uint32_t b0 = *(const uint32_t*)(sm.xb + base);
                uint32_t b1 = *(const uint32_t*)(sm.xb + base + 16);
                mma16816(d[tg], ah, b0, b1);
                mma16816(d[tg], al, b0, b1);
            }
        }
    }

    // ---- epilogue: stage D to smem, then coalesced partial store ----
    __syncthreads();
    #pragma unroll
    for (int tg = 0; tg < 4; tg++) {
        int tok = tg * 8 + l4 * 2;
        int nl  = wid * 16 + g4;
        sm.res[tok][nl]         = d[tg][0];
        sm.res[tok + 1][nl]     = d[tg][1];
        sm.res[tok][nl + 8]     = d[tg][2];
        sm.res[tok + 1][nl + 8] = d[tg][3];
    }
    __syncthreads();
    float* pb = g_part[kq];
    #pragma unroll
    for (int i = 0; i < 4; i++) {
        int idx = tid + i * THREADS;              // 0..1023 float4s
        int tok = idx >> 5, seg = idx & 31;
        float4 v = *(const float4*)(&sm.res[tok][seg * 4]);
        *(float4*)(pb + (size_t)tok * NN + nb + seg * 4) = v;
    }
}

__global__ __launch_bounds__(256)
void reduce_out(const float* __restrict__ bias, float* __restrict__ out)
{
    int i = blockIdx.x * 256 + threadIdx.x;       // float4 index
    const int TOT4 = MM * NN / 4;
    if (i < TOT4) {
        float4 a = make_float4(0.f, 0.f, 0.f, 0.f);
        #pragma unroll
        for (int p = 0; p < KSPLIT; p++) {
            float4 v = __ldg(&((const float4*)g_part[p])[i]);
            a.x += v.x; a.y += v.y; a.z += v.z; a.w += v.w;
        }
        float4 b = __ldg(&((const float4*)bias)[i % (NN / 4)]);
        a.x += b.x; a.y += b.y; a.z += b.z; a.w += b.w;
        ((float4*)out)[i] = a;
    }
}

extern "C" void kernel_launch(void* const* d_in, const int* in_sizes, int n_in,
                              void* d_out, int out_size) {
    const float* x    = (const float*)d_in[0];
    const int*   wgt  = (const int*)d_in[1];
    const float* sz   = (const float*)d_in[2];
    const float* bias = (const float*)d_in[3];
    float* out = (float*)d_out;
    split_x<<<(MM * KK / 4 + 255) / 256, 256>>>(x);
    qlinear_mma<<<dim3(NN / BN, KSPLIT), THREADS>>>(wgt, sz);
    reduce_out<<<(MM * NN / 4 + 255) / 256, 256>>>(bias, out);
}

// round 14
// speedup vs baseline: 1.1024x; 1.1024x over previous
#include <cuda_runtime.h>
#include <cuda_bf16.h>
#include <cstdint>

// QLinear int4 dequant GEMM: mma.sync bf16 3-product split + cp.async weight pipeline.
// D[n_out, tok] = W[n,k] @ X^T.  Weights GMEM->smem via 3-stage cp.async (8KB/stage),
// dequant from smem with permuted-k fragments (int4 LDS.128 per row-pair).

#define MM 32
#define KK 4096
#define NN 11008
#define BN 128
#define KSPLIT 8
#define KSPAN (KK / KSPLIT)    // 512
#define KC 128
#define THREADS 256
#define XS 288                 // x smem row stride (bytes): 256 data + 32 pad (72w = 8 mod 32)
#define RS 132                 // res row stride (floats)
#define PF 3                   // cp.async pipeline stages
#define NST (KSPAN / 16)       // 32 k16-steps per CTA
#define WSTAGE (BN * 64)       // 8192 B per stage (128 rows x 16 ints)

__device__ __nv_bfloat16 g_xh[MM * KK];
__device__ __nv_bfloat16 g_xl[MM * KK];
__device__ float g_part[KSPLIT][MM * NN];

__global__ __launch_bounds__(256)
void split_x(const float* __restrict__ x) {
    int i = blockIdx.x * 256 + threadIdx.x;       // float4 index, 32768 total
    if (i < MM * KK / 4) {
        float4 f = ((const float4*)x)[i];
        __nv_bfloat162 h0 = __floats2bfloat162_rn(f.x, f.y);
        __nv_bfloat162 h1 = __floats2bfloat162_rn(f.z, f.w);
        float r0 = f.x - __bfloat162float(h0.x);
        float r1 = f.y - __bfloat162float(h0.y);
        float r2 = f.z - __bfloat162float(h1.x);
        float r3 = f.w - __bfloat162float(h1.y);
        __nv_bfloat162 l0 = __floats2bfloat162_rn(r0, r1);
        __nv_bfloat162 l1 = __floats2bfloat162_rn(r2, r3);
        ((uint2*)g_xh)[i] = make_uint2(*(uint32_t*)&h0, *(uint32_t*)&h1);
        ((uint2*)g_xl)[i] = make_uint2(*(uint32_t*)&l0, *(uint32_t*)&l1);
    }
}

__device__ __forceinline__ uint32_t s2u(const void* p) {
    uint32_t a;
    asm("{ .reg .u64 t; cvta.to.shared.u64 t, %1; cvt.u32.u64 %0, t; }" : "=r"(a) : "l"(p));
    return a;
}

__device__ __forceinline__ float dq1(int q, float s, float z) {
    float f = __int_as_float(q | 0x4B000000);   // 2^23 + q
    float t = f - 8388616.0f;                   // exact (Sterbenz): q - 8
    return __fmaf_rn(t, s, z);
}

__device__ __forceinline__ void dqpair(int qa, int qb, float2 szv, uint32_t& hi, uint32_t& lo) {
    float s = szv.x, z = szv.y;
    float w0 = dq1(qa, s, z);
    float w1 = dq1(qb, s, z);
    uint32_t h;
    asm("cvt.rn.bf16x2.f32 %0, %1, %2;" : "=r"(h) : "f"(w1), "f"(w0));
    float h0 = __uint_as_float(h << 16);
    float h1 = __uint_as_float(h & 0xFFFF0000u);
    float l0 = w0 - h0;
    float l1 = w1 - h1;
    uint32_t l;
    asm("cvt.rn.bf16x2.f32 %0, %1, %2;" : "=r"(l) : "f"(l1), "f"(l0));
    hi = h; lo = l;
}

__device__ __forceinline__ void mma16816(float* d, const uint32_t* a, uint32_t b0, uint32_t b1) {
    asm volatile(
        "mma.sync.aligned.m16n8k16.row.col.f32.bf16.bf16.f32 "
        "{%0,%1,%2,%3}, {%4,%5,%6,%7}, {%8,%9}, {%0,%1,%2,%3};"
        : "+f"(d[0]), "+f"(d[1]), "+f"(d[2]), "+f"(d[3])
        : "r"(a[0]), "r"(a[1]), "r"(a[2]), "r"(a[3]), "r"(b0), "r"(b1));
}

__global__ __launch_bounds__(THREADS)
void qlinear_mma(const int* __restrict__ w, const float* __restrict__ sz)
{
    __shared__ __align__(16) char wsm[PF * WSTAGE];     // 24576 B
    __shared__ union {
        struct { char hi[MM * XS]; char lo[MM * XS]; } x;   // 18432 B
        float res[MM][RS];                                   // 16896 B
    } sm;

    const int tid  = threadIdx.x;
    const int lane = tid & 31;
    const int wid  = tid >> 5;
    const int nb   = blockIdx.x * BN;
    const int kq   = blockIdx.y;
    const int kbeg = kq * KSPAN;
    const int g4   = lane >> 2;   // 0..7
    const int l4   = lane & 3;    // 0..3

    // cp.async mapping: thread copies two 16B chunks per stage
    const int rA = tid >> 2, sgA = tid & 3;
    const int rB = rA + 64;
    const int* gA = w + (size_t)(nb + rA) * KK + kbeg + sgA * 4;
    const int* gB = w + (size_t)(nb + rB) * KK + kbeg + sgA * 4;
    const uint32_t wbase = s2u(wsm);
    const uint32_t sAo = wbase + rA * 64 + sgA * 16;
    const uint32_t sBo = wbase + rB * 64 + sgA * 16;

#define ISSUE(GST) do {                                                          \
    uint32_t _so = (uint32_t)(((GST) % PF) * WSTAGE);                            \
    asm volatile("cp.async.cg.shared.global [%0], [%1], 16;"                     \
                 :: "r"(sAo + _so), "l"(gA + (GST) * 16) : "memory");            \
    asm volatile("cp.async.cg.shared.global [%0], [%1], 16;"                     \
                 :: "r"(sBo + _so), "l"(gB + (GST) * 16) : "memory");            \
    asm volatile("cp.async.commit_group;" ::: "memory");                         \
} while (0)

    ISSUE(0);
    ISSUE(1);

    const int r0 = nb + wid * 16 + g4;
    const float2* szp = (const float2*)sz;
    const int lrow = wid * 16 + g4;

    float d[4][4];
    #pragma unroll
    for (int tg = 0; tg < 4; tg++)
        #pragma unroll
        for (int j = 0; j < 4; j++) d[tg][j] = 0.f;

    for (int c = 0; c < KSPAN / KC; c++) {
        const int kc = c * KC;
        __syncthreads();   // previous chunk's x fully consumed
        // ---- stage x chunk (pre-split bf16 hi/lo) ----
        #pragma unroll
        for (int i = 0; i < 2; i++) {
            int idx = tid + i * THREADS;
            int tok = idx >> 4, seg = idx & 15;
            size_t s = (size_t)tok * KK + kbeg + kc + seg * 8;
            *(uint4*)(sm.x.hi + tok * XS + seg * 16) = *(const uint4*)(g_xh + s);
            *(uint4*)(sm.x.lo + tok * XS + seg * 16) = *(const uint4*)(g_xl + s);
        }
        // ---- scales for this chunk's 4 groups ----
        float2 sc0[4], sc1[4];
        {
            int gb = (kbeg + kc) >> 5;
            #pragma unroll
            for (int g = 0; g < 4; g++) {
                sc0[g] = szp[(size_t)(gb + g) * NN + r0];
                sc1[g] = szp[(size_t)(gb + g) * NN + r0 + 8];
            }
        }

        #pragma unroll
        for (int st = 0; st < 8; st++) {
            const int gst = c * 8 + st;
            asm volatile("cp.async.wait_group 1;" ::: "memory");
            __syncthreads();   // stage gst visible to all; stage gst-1 consumed by all
            if (gst + 2 < NST) ISSUE(gst + 2);

            // ---- A fragments from weight smem (permuted k: lane l4 owns 4l4..4l4+3) ----
            const char* wsp = wsm + (gst % PF) * WSTAGE;
            int4 q0 = *(const int4*)(wsp + lrow * 64 + l4 * 16);
            int4 q1 = *(const int4*)(wsp + (lrow + 8) * 64 + l4 * 16);
            float2 s0 = sc0[st >> 1];
            float2 s1 = sc1[st >> 1];

            uint32_t ah[4], al[4];
            dqpair(q0.x, q0.y, s0, ah[0], al[0]);   // a0: row r0,   k 4l4..+1
            dqpair(q1.x, q1.y, s1, ah[1], al[1]);   // a1: row r0+8
            dqpair(q0.z, q0.w, s0, ah[2], al[2]);   // a2: row r0,   k 4l4+2..+3
            dqpair(q1.z, q1.w, s1, ah[3], al[3]);   // a3: row r0+8

            #pragma unroll
            for (int tg = 0; tg < 4; tg++) {
                int base = (tg * 8 + g4) * XS + st * 32 + l4 * 8;
                uint2 bh = *(const uint2*)(sm.x.hi + base);
                uint2 bl = *(const uint2*)(sm.x.lo + base);
                mma16816(d[tg], ah, bh.x, bh.y);
                mma16816(d[tg], ah, bl.x, bl.y);
                mma16816(d[tg], al, bh.x, bh.y);
            }
        }
    }

    // ---- epilogue: stage D to smem, then coalesced partial store ----
    __syncthreads();
    #pragma unroll
    for (int tg = 0; tg < 4; tg++) {
        int tok = tg * 8 + l4 * 2;
        int nl  = wid * 16 + g4;
        sm.res[tok][nl]         = d[tg][0];
        sm.res[tok + 1][nl]     = d[tg][1];
        sm.res[tok][nl + 8]     = d[tg][2];
        sm.res[tok + 1][nl + 8] = d[tg][3];
    }
    __syncthreads();
    float* pb = g_part[kq];
    #pragma unroll
    for (int i = 0; i < 4; i++) {
        int idx = tid + i * THREADS;
        int tok = idx >> 5, seg = idx & 31;
        float4 v = *(const float4*)(&sm.res[tok][seg * 4]);
        *(float4*)(pb + (size_t)tok * NN + nb + seg * 4) = v;
    }
}

__global__ __launch_bounds__(256)
void reduce_out(const float* __restrict__ bias, float* __restrict__ out)
{
    int i = blockIdx.x * 256 + threadIdx.x;
    const int TOT4 = MM * NN / 4;
    if (i < TOT4) {
        float4 a = make_float4(0.f, 0.f, 0.f, 0.f);
        #pragma unroll
        for (int p = 0; p < KSPLIT; p++) {
            float4 v = __ldg(&((const float4*)g_part[p])[i]);
            a.x += v.x; a.y += v.y; a.z += v.z; a.w += v.w;
        }
        float4 b = __ldg(&((const float4*)bias)[i % (NN / 4)]);
        a.x += b.x; a.y += b.y; a.z += b.z; a.w += b.w;
        ((float4*)out)[i] = a;
    }
}

extern "C" void kernel_launch(void* const* d_in, const int* in_sizes, int n_in,
                              void* d_out, int out_size) {
    const float* x    = (const float*)d_in[0];
    const int*   wgt  = (const int*)d_in[1];
    const float* sz   = (const float*)d_in[2];
    const float* bias = (const float*)d_in[3];
    float* out = (float*)d_out;
    split_x<<<(MM * KK / 4 + 255) / 256, 256>>>(x);
    qlinear_mma<<<dim3(NN / BN, KSPLIT), THREADS>>>(wgt, sz);
    reduce_out<<<(MM * NN / 4 + 255) / 256, 256>>>(bias, out);
}